// round 7
// baseline (speedup 1.0000x reference)
#include <cuda_runtime.h>
#include <cuda_bf16.h>
#include <cstdint>

// LSTM  B=64, T=1024, D=512, U=512, OUT=4
#define BATCH    64
#define TSTEPS   1024
#define DIN      512
#define UNITS    512
#define FOURU    2048
#define NCTA     256
#define TPB      128
#define NBG      4
#define NMTILE   4096
#define NKSTEP   32

// recurrence smem (floats): CTA = 8 units x 16 batches
#define SM_R4     0        // [128 kq][8 u][16 e] e=g*4+kl : 16384
#define SM_H4     16384    // [128 kq][68 pad]             : 8704
#define SM_XZ     25088    // [2][4 g][8 u][17 pad]        : 1088
#define SM_FLOATS 26176
#define SM_BYTES  (SM_FLOATS * 4)     // 104704 B -> 2 CTAs/SM

__device__ float    g_xz[(size_t)BATCH * TSTEPS * FOURU];       // 512 MB
__device__ uint4    g_Afrag[(size_t)NMTILE * NKSTEP * 2 * 32];  // 134 MB
__device__ uint4    g_Wfrag[(size_t)NKSTEP * 2 * 64 * 32 * 2];  // 8 MB
__device__ float    g_h[2][BATCH][UNITS];
__device__ unsigned g_sub[NBG][8][8];      // two-level barrier: 8 sub-counters
__device__ unsigned g_master[NBG][32];
__device__ unsigned g_gen[NBG][32];

typedef unsigned long long u64t;
__device__ __forceinline__ void ffma2(u64t& d, u64t a, u64t b) {
    asm("fma.rn.f32x2 %0, %1, %2, %0;" : "+l"(d) : "l"(a), "l"(b));
}
__device__ __forceinline__ float2 unpack2(u64t v) {
    float2 f; asm("mov.b64 {%0, %1}, %2;" : "=f"(f.x), "=f"(f.y) : "l"(v)); return f;
}
__device__ __forceinline__ float fsig(float x) {
    return __fdividef(1.f, 1.f + __expf(-x));
}
__device__ __forceinline__ float ftanh(float x) {
    return 1.f - __fdividef(2.f, __expf(2.f * x) + 1.f);
}
__device__ __forceinline__ unsigned atom_add_acqrel(unsigned* p, unsigned v) {
    unsigned old;
    asm volatile("atom.acq_rel.gpu.global.add.u32 %0, [%1], %2;"
                 : "=r"(old) : "l"(p), "r"(v) : "memory");
    return old;
}
__device__ __forceinline__ void st_release(unsigned* p, unsigned v) {
    asm volatile("st.release.gpu.global.u32 [%0], %1;" :: "l"(p), "r"(v) : "memory");
}
__device__ __forceinline__ unsigned ld_acquire(const unsigned* p) {
    unsigned v;
    asm volatile("ld.acquire.gpu.global.u32 %0, [%1];" : "=r"(v) : "l"(p) : "memory");
    return v;
}
__device__ __forceinline__ uint32_t pack_split_hi(float a, float b) {
    __nv_bfloat16 ha = __float2bfloat16(a), hb = __float2bfloat16(b);
    return (uint32_t)*(uint16_t*)&ha | ((uint32_t)*(uint16_t*)&hb << 16);
}
__device__ __forceinline__ uint32_t pack_split_lo(float a, float b) {
    __nv_bfloat16 ha = __float2bfloat16(a), hb = __float2bfloat16(b);
    __nv_bfloat16 la = __float2bfloat16(a - __bfloat162float(ha));
    __nv_bfloat16 lb = __float2bfloat16(b - __bfloat162float(hb));
    return (uint32_t)*(uint16_t*)&la | ((uint32_t)*(uint16_t*)&lb << 16);
}

__global__ void init_kernel() {
    int i = blockIdx.x * blockDim.x + threadIdx.x;
    if (i < 2 * BATCH * UNITS) ((float*)g_h)[i] = 0.f;
    if (i < NBG * 8 * 8) ((unsigned*)g_sub)[i] = 0u;
    if (i < NBG * 32) { ((unsigned*)g_master)[i] = 0u; ((unsigned*)g_gen)[i] = 0u; }
}

// ---- prep A (unchanged from R6) -------------------------------------------
__global__ __launch_bounds__(256) void prep_A(const float* __restrict__ A) {
    int f = blockIdx.x * 256 + threadIdx.x;
    int t = f & 31, ks = (f >> 5) & 31, mt = f >> 10;
    uint32_t hi[4], lo[4];
#pragma unroll
    for (int r = 0; r < 4; r++) {
        int m  = mt * 16 + (r & 1) * 8 + (t >> 2);
        int k0 = ks * 16 + ((r & 2) << 2) + ((t & 3) << 1);
        float2 av = *(const float2*)(A + (size_t)m * DIN + k0);
        hi[r] = pack_split_hi(av.x, av.y);
        lo[r] = pack_split_lo(av.x, av.y);
    }
    size_t ib = ((size_t)mt * 32 + ks) * 2;
    g_Afrag[ib * 32 + t]       = make_uint4(hi[0], hi[1], hi[2], hi[3]);
    g_Afrag[(ib + 1) * 32 + t] = make_uint4(lo[0], lo[1], lo[2], lo[3]);
}

// ---- prep W (unchanged from R6) -------------------------------------------
__global__ __launch_bounds__(256) void prep_W(const float* __restrict__ W) {
    int f = blockIdx.x * 256 + threadIdx.x;
    int t = f & 31, ngrp = (f >> 5) & 63, ks = f >> 11;
    uint32_t hi[8], lo[8];
#pragma unroll
    for (int nblk = 0; nblk < 4; nblk++)
#pragma unroll
        for (int reg = 0; reg < 2; reg++) {
            int k0 = ks * 16 + reg * 8 + (t & 3) * 2;
            int n  = ngrp * 32 + nblk * 8 + (t >> 2);
            float w0 = W[(size_t)k0 * FOURU + n];
            float w1 = W[(size_t)(k0 + 1) * FOURU + n];
            hi[nblk * 2 + reg] = pack_split_hi(w0, w1);
            lo[nblk * 2 + reg] = pack_split_lo(w0, w1);
        }
    size_t wb = (((size_t)ks * 2 + 0) * 64 + ngrp) * 32 + t;
    size_t wl = (((size_t)ks * 2 + 1) * 64 + ngrp) * 32 + t;
    g_Wfrag[wb * 2]     = make_uint4(hi[0], hi[1], hi[2], hi[3]);
    g_Wfrag[wb * 2 + 1] = make_uint4(hi[4], hi[5], hi[6], hi[7]);
    g_Wfrag[wl * 2]     = make_uint4(lo[0], lo[1], lo[2], lo[3]);
    g_Wfrag[wl * 2 + 1] = make_uint4(lo[4], lo[5], lo[6], lo[7]);
}

#define MMA16816(c, a, b0v, b1v)                                              \
    asm volatile(                                                             \
        "mma.sync.aligned.m16n8k16.row.col.f32.bf16.bf16.f32 "                \
        "{%0,%1,%2,%3}, {%4,%5,%6,%7}, {%8,%9}, {%0,%1,%2,%3};"               \
        : "+f"((c)[0]), "+f"((c)[1]), "+f"((c)[2]), "+f"((c)[3])              \
        : "r"((a).x), "r"((a).y), "r"((a).z), "r"((a).w),                     \
          "r"(b0v), "r"(b1v))

// ---- GEMM (unchanged from R6) ---------------------------------------------
__global__ __launch_bounds__(256) void gemm_mma(const float* __restrict__ bias) {
    const int tid = threadIdx.x;
    const int t = tid & 31, wid = tid >> 5;
    const int wm = wid & 1, wn = wid >> 1;
    const int mtb = blockIdx.y * 8 + wm * 4;
    const int ngrp = blockIdx.x * 4 + wn;

    float acc[4][4][4];
#pragma unroll
    for (int mi = 0; mi < 4; mi++)
#pragma unroll
        for (int ni = 0; ni < 4; ni++)
#pragma unroll
            for (int c = 0; c < 4; c++) acc[mi][ni][c] = 0.f;

#pragma unroll 2
    for (int ks = 0; ks < NKSTEP; ks++) {
        uint4 ah[4], al[4];
#pragma unroll
        for (int mi = 0; mi < 4; mi++) {
            size_t ib = ((size_t)(mtb + mi) * 32 + ks) * 2;
            ah[mi] = g_Afrag[ib * 32 + t];
            al[mi] = g_Afrag[(ib + 1) * 32 + t];
        }
        size_t wb = (((size_t)ks * 2 + 0) * 64 + ngrp) * 32 + t;
        size_t wl = (((size_t)ks * 2 + 1) * 64 + ngrp) * 32 + t;
        uint4 bh0 = g_Wfrag[wb * 2], bh1 = g_Wfrag[wb * 2 + 1];
        uint4 bl0 = g_Wfrag[wl * 2], bl1 = g_Wfrag[wl * 2 + 1];
        uint32_t bh[8] = {bh0.x, bh0.y, bh0.z, bh0.w, bh1.x, bh1.y, bh1.z, bh1.w};
        uint32_t bl[8] = {bl0.x, bl0.y, bl0.z, bl0.w, bl1.x, bl1.y, bl1.z, bl1.w};

#pragma unroll
        for (int mi = 0; mi < 4; mi++)
#pragma unroll
            for (int ni = 0; ni < 4; ni++) {
                MMA16816(acc[mi][ni], ah[mi], bh[ni * 2], bh[ni * 2 + 1]);
                MMA16816(acc[mi][ni], ah[mi], bl[ni * 2], bl[ni * 2 + 1]);
                MMA16816(acc[mi][ni], al[mi], bh[ni * 2], bh[ni * 2 + 1]);
            }
    }

    const int colbase = blockIdx.x * 128 + wn * 32 + (t & 3) * 2;
    const int rowbase = blockIdx.y * 128 + wm * 64 + (t >> 2);
    float2 bv[4];
#pragma unroll
    for (int ni = 0; ni < 4; ni++)
        bv[ni] = *(const float2*)(bias + colbase + ni * 8);
#pragma unroll
    for (int mi = 0; mi < 4; mi++) {
        int r0 = rowbase + mi * 16;
#pragma unroll
        for (int ni = 0; ni < 4; ni++) {
            int col = colbase + ni * 8;
            float2 o0 = make_float2(acc[mi][ni][0] + bv[ni].x,
                                    acc[mi][ni][1] + bv[ni].y);
            float2 o1 = make_float2(acc[mi][ni][2] + bv[ni].x,
                                    acc[mi][ni][3] + bv[ni].y);
            __stcs((float2*)(g_xz + (size_t)r0 * FOURU + col), o0);
            __stcs((float2*)(g_xz + (size_t)(r0 + 8) * FOURU + col), o1);
        }
    }
}

// ---- persistent LSTM recurrence: 256 CTAs x 128 thr, 2 CTAs/SM ------------
// CTA c: bg = c>>6 (batch group, 16 batches), ug = c&63 (8 units).
// Classic placement pairs bid with bid+148 => different bg on the same SM,
// so one CTA's barrier wait overlaps the other's compute.
__global__ __launch_bounds__(TPB, 2) void lstm_recur(const float* __restrict__ R)
{
    extern __shared__ float sm[];
    float* R4  = sm + SM_R4;
    float* h4  = sm + SM_H4;
    float* xzs = sm + SM_XZ;

    const int tid = threadIdx.x;
    const int c = blockIdx.x;
    const int bg = c >> 6, ug = c & 63;
    const int u0 = ug * 8, b0 = bg * 16;
    const int b_l = tid & 15, u_l = tid >> 4;   // u_l in 0..7

    // R4[kq][u][g*4+kl] = R[(kq*4+kl)][g*512 + u0 + u]
    for (int i = tid; i < 16384; i += TPB) {
        int kq = i >> 7, u = (i >> 4) & 7, e = i & 15, g = e >> 2, kl = e & 3;
        R4[i] = R[(size_t)(kq * 4 + kl) * FOURU + g * UNITS + u0 + u];
    }

    // xz staging: thread -> (pb 16, pg 4, pq 2); layout [2][g*136 + row*17 + b]
    const int pb = tid >> 3, pg = (tid >> 1) & 3, pq = tid & 1;
    const float* xz_thread = g_xz + (size_t)(b0 + pb) * TSTEPS * FOURU
                             + pg * UNITS + u0 + pq * 4;
    {
        float4 v = __ldcs((const float4*)xz_thread);
        float vv[4] = {v.x, v.y, v.z, v.w};
#pragma unroll
        for (int j = 0; j < 4; j++)
            xzs[pg * 136 + (pq * 4 + j) * 17 + pb] = vv[j];
    }
    __syncthreads();

    // h staging: sb = batch (0..15), kqb = quad col (0..7), 16 quads/thread
    const int sb = tid >> 3, kqb = tid & 7;
    unsigned* subcnt  = &g_sub[bg][ug >> 3][0];
    unsigned* master  = &g_master[bg][0];
    unsigned* gen     = &g_gen[bg][0];

    float c_state = 0.f;

    for (int t = 0; t < TSTEPS; t++) {
        float4 xnext = make_float4(0.f, 0.f, 0.f, 0.f);
        if (t + 1 < TSTEPS)
            xnext = __ldcs((const float4*)(xz_thread + (size_t)(t + 1) * FOURU));

        // load + stage h(t): 16 float4 per thread in two register batches
        const float* hsrc = &g_h[t & 1][b0 + sb][0];
        float4 hq[8];
#pragma unroll
        for (int r = 0; r < 8; r++)
            hq[r] = __ldcg((const float4*)(hsrc + (kqb + 8 * r) * 4));
#pragma unroll
        for (int r = 0; r < 8; r++)
            *(float4*)&h4[(kqb + 8 * r) * 68 + sb * 4] = hq[r];
#pragma unroll
        for (int r = 0; r < 8; r++)
            hq[r] = __ldcg((const float4*)(hsrc + (kqb + 8 * (r + 8)) * 4));
#pragma unroll
        for (int r = 0; r < 8; r++)
            *(float4*)&h4[(kqb + 8 * (r + 8)) * 68 + sb * 4] = hq[r];
        __syncthreads();

        // 4 gate dot-products, f32x2 over k pairs, ILP-friendly order
        u64t a0 = 0ull, a1 = 0ull, a2 = 0ull, a3 = 0ull;
        const float* hrow = h4 + b_l * 4;
        const float* rrow = R4 + u_l * 16;
#pragma unroll 8
        for (int kq = 0; kq < 128; kq++) {
            ulonglong2 hh = *(const ulonglong2*)(hrow + kq * 68);
            ulonglong2 r0 = *(const ulonglong2*)(rrow + kq * 128);
            ulonglong2 r1 = *(const ulonglong2*)(rrow + kq * 128 + 4);
            ulonglong2 r2 = *(const ulonglong2*)(rrow + kq * 128 + 8);
            ulonglong2 r3 = *(const ulonglong2*)(rrow + kq * 128 + 12);
            ffma2(a0, r0.x, hh.x); ffma2(a1, r1.x, hh.x);
            ffma2(a2, r2.x, hh.x); ffma2(a3, r3.x, hh.x);
            ffma2(a0, r0.y, hh.y); ffma2(a1, r1.y, hh.y);
            ffma2(a2, r2.y, hh.y); ffma2(a3, r3.y, hh.y);
        }

        const float* xb = xzs + (t & 1) * 544 + u_l * 17 + b_l;
        float2 p;
        p = unpack2(a0); float z1 = p.x + p.y + xb[0];
        p = unpack2(a1); float z2 = p.x + p.y + xb[136];
        p = unpack2(a2); float z3 = p.x + p.y + xb[272];
        p = unpack2(a3); float z4 = p.x + p.y + xb[408];

        float v1 = ftanh(z1);
        float v2 = fsig(z2);
        float v3 = fsig(z3);
        float v4 = fsig(z4);
        c_state = v1 * v2 + v3 * c_state;
        float hnew = v4 * ftanh(c_state);

        __stcg(&g_h[(t + 1) & 1][b0 + b_l][u0 + u_l], hnew);

        if (t + 1 < TSTEPS) {
            float vv[4] = {xnext.x, xnext.y, xnext.z, xnext.w};
            float* dst = xzs + ((t + 1) & 1) * 544;
#pragma unroll
            for (int j = 0; j < 4; j++)
                dst[pg * 136 + (pq * 4 + j) * 17 + pb] = vv[j];
        }

        // ---- two-level acq_rel barrier (64 CTAs/group, monotonic counters)
        __syncthreads();
        if (tid == 0) {
            unsigned ps = atom_add_acqrel(subcnt, 1u);
            if ((ps & 7u) == 7u) {
                unsigned pm = atom_add_acqrel(master, 1u);
                if ((pm & 7u) == 7u)
                    st_release(gen, (unsigned)(t + 1));
            }
            while (ld_acquire(gen) < (unsigned)(t + 1)) { }
        }
        __syncthreads();
    }
}

// ---- final dense + softmax --------------------------------------------------
__global__ void fc_softmax(const float* __restrict__ fc_w,
                           const float* __restrict__ fc_b,
                           float* __restrict__ out)
{
    const int b = blockIdx.x;
    const int l = threadIdx.x;
    float a0 = 0.f, a1 = 0.f, a2 = 0.f, a3 = 0.f;
    const float* hg = &g_h[0][b][0];   // t=1023 wrote parity 0
    for (int k = l * 16; k < l * 16 + 16; k += 4) {
        float4 hv = *(const float4*)(hg + k);
        float hx[4] = {hv.x, hv.y, hv.z, hv.w};
#pragma unroll
        for (int q = 0; q < 4; q++) {
            float4 wv = *(const float4*)&fc_w[(k + q) * 4];
            a0 += hx[q] * wv.x; a1 += hx[q] * wv.y;
            a2 += hx[q] * wv.z; a3 += hx[q] * wv.w;
        }
    }
#pragma unroll
    for (int o = 16; o > 0; o >>= 1) {
        a0 += __shfl_down_sync(0xffffffffu, a0, o);
        a1 += __shfl_down_sync(0xffffffffu, a1, o);
        a2 += __shfl_down_sync(0xffffffffu, a2, o);
        a3 += __shfl_down_sync(0xffffffffu, a3, o);
    }
    if (l == 0) {
        float z0 = a0 + fc_b[0], z1 = a1 + fc_b[1];
        float z2 = a2 + fc_b[2], z3 = a3 + fc_b[3];
        float m = fmaxf(fmaxf(z0, z1), fmaxf(z2, z3));
        float e0 = __expf(z0 - m), e1 = __expf(z1 - m);
        float e2 = __expf(z2 - m), e3 = __expf(z3 - m);
        float inv = __fdividef(1.f, e0 + e1 + e2 + e3);
        out[b * 4 + 0] = e0 * inv;
        out[b * 4 + 1] = e1 * inv;
        out[b * 4 + 2] = e2 * inv;
        out[b * 4 + 3] = e3 * inv;
    }
}

// ---------------------------------------------------------------------------
extern "C" void kernel_launch(void* const* d_in, const int* in_sizes, int n_in,
                              void* d_out, int out_size)
{
    const float* tx      = (const float*)d_in[0];
    const float* kernelW = (const float*)d_in[1];
    const float* R       = (const float*)d_in[2];
    const float* bias    = (const float*)d_in[3];
    const float* fc_w    = (const float*)d_in[4];
    const float* fc_b    = (const float*)d_in[5];
    float* out           = (float*)d_out;

    cudaFuncSetAttribute(lstm_recur,
                         cudaFuncAttributeMaxDynamicSharedMemorySize, SM_BYTES);

    init_kernel<<<(2 * BATCH * UNITS + 255) / 256, 256>>>();
    prep_A<<<16384, 256>>>(tx);
    prep_W<<<256, 256>>>(kernelW);
    gemm_mma<<<dim3(16, 512), 256>>>(bias);
    lstm_recur<<<NCTA, TPB, SM_BYTES>>>(R);
    fc_softmax<<<BATCH, 32>>>(fc_w, fc_b, out);
    (void)in_sizes; (void)n_in; (void)out_size;
}

// round 8
// speedup vs baseline: 1.1409x; 1.1409x over previous
#include <cuda_runtime.h>
#include <cuda_bf16.h>
#include <cstdint>

// LSTM  B=64, T=1024, D=512, U=512, OUT=4
#define BATCH    64
#define TSTEPS   1024
#define DIN      512
#define UNITS    512
#define FOURU    2048
#define NCTA     128
#define TPB      512
#define NBG      4
#define GROUP_CTAS 32
#define NMTILE   4096
#define NKSTEP   32

// recurrence smem (floats)
#define SM_R4     0        // [128 kq][16 u][16 e] e=g*4+kl : 32768
#define SM_H4     32768    // [128 kq][68 pad]              : 8704
#define SM_XZ     41472    // [2][4 g][16 u][17 pad]        : 2176
#define SM_RED    43648    // [256][12]                     : 3072
#define SM_FLOATS 46720
#define SM_BYTES  (SM_FLOATS * 4)   // 186,880 B -> 1 CTA/SM

__device__ float    g_xz[(size_t)BATCH * TSTEPS * FOURU];
__device__ uint4    g_Afrag[(size_t)NMTILE * NKSTEP * 2 * 32];
__device__ uint4    g_Wfrag[(size_t)NKSTEP * 2 * 64 * 32 * 2];
__device__ float    g_h[2][BATCH][UNITS];
__device__ unsigned g_arrive[NBG * 32];
__device__ unsigned g_gen[NBG * 32];

typedef unsigned long long u64t;
__device__ __forceinline__ void ffma2(u64t& d, u64t a, u64t b) {
    asm("fma.rn.f32x2 %0, %1, %2, %0;" : "+l"(d) : "l"(a), "l"(b));
}
__device__ __forceinline__ float2 unpack2(u64t v) {
    float2 f; asm("mov.b64 {%0, %1}, %2;" : "=f"(f.x), "=f"(f.y) : "l"(v)); return f;
}
__device__ __forceinline__ float fsig(float x) {
    return __fdividef(1.f, 1.f + __expf(-x));
}
__device__ __forceinline__ float ftanh(float x) {
    return 1.f - __fdividef(2.f, __expf(2.f * x) + 1.f);
}
__device__ __forceinline__ unsigned atom_add_acqrel(unsigned* p, unsigned v) {
    unsigned old;
    asm volatile("atom.acq_rel.gpu.global.add.u32 %0, [%1], %2;"
                 : "=r"(old) : "l"(p), "r"(v) : "memory");
    return old;
}
__device__ __forceinline__ void st_release(unsigned* p, unsigned v) {
    asm volatile("st.release.gpu.global.u32 [%0], %1;" :: "l"(p), "r"(v) : "memory");
}
__device__ __forceinline__ unsigned ld_acquire(const unsigned* p) {
    unsigned v;
    asm volatile("ld.acquire.gpu.global.u32 %0, [%1];" : "=r"(v) : "l"(p) : "memory");
    return v;
}
__device__ __forceinline__ uint32_t pack_split_hi(float a, float b) {
    __nv_bfloat16 ha = __float2bfloat16(a), hb = __float2bfloat16(b);
    return (uint32_t)*(uint16_t*)&ha | ((uint32_t)*(uint16_t*)&hb << 16);
}
__device__ __forceinline__ uint32_t pack_split_lo(float a, float b) {
    __nv_bfloat16 ha = __float2bfloat16(a), hb = __float2bfloat16(b);
    __nv_bfloat16 la = __float2bfloat16(a - __bfloat162float(ha));
    __nv_bfloat16 lb = __float2bfloat16(b - __bfloat162float(hb));
    return (uint32_t)*(uint16_t*)&la | ((uint32_t)*(uint16_t*)&lb << 16);
}

__global__ void init_kernel() {
    int i = blockIdx.x * blockDim.x + threadIdx.x;
    if (i < 2 * BATCH * UNITS) ((float*)g_h)[i] = 0.f;
    if (i < NBG * 32) { g_arrive[i] = 0u; g_gen[i] = 0u; }
}

// ---- prep A ----------------------------------------------------------------
__global__ __launch_bounds__(256) void prep_A(const float* __restrict__ A) {
    int f = blockIdx.x * 256 + threadIdx.x;
    int t = f & 31, ks = (f >> 5) & 31, mt = f >> 10;
    uint32_t hi[4], lo[4];
#pragma unroll
    for (int r = 0; r < 4; r++) {
        int m  = mt * 16 + (r & 1) * 8 + (t >> 2);
        int k0 = ks * 16 + ((r & 2) << 2) + ((t & 3) << 1);
        float2 av = *(const float2*)(A + (size_t)m * DIN + k0);
        hi[r] = pack_split_hi(av.x, av.y);
        lo[r] = pack_split_lo(av.x, av.y);
    }
    size_t ib = ((size_t)mt * 32 + ks) * 2;
    g_Afrag[ib * 32 + t]       = make_uint4(hi[0], hi[1], hi[2], hi[3]);
    g_Afrag[(ib + 1) * 32 + t] = make_uint4(lo[0], lo[1], lo[2], lo[3]);
}

// ---- prep W ----------------------------------------------------------------
__global__ __launch_bounds__(256) void prep_W(const float* __restrict__ W) {
    int f = blockIdx.x * 256 + threadIdx.x;
    int t = f & 31, ngrp = (f >> 5) & 63, ks = f >> 11;
    uint32_t hi[8], lo[8];
#pragma unroll
    for (int nblk = 0; nblk < 4; nblk++)
#pragma unroll
        for (int reg = 0; reg < 2; reg++) {
            int k0 = ks * 16 + reg * 8 + (t & 3) * 2;
            int n  = ngrp * 32 + nblk * 8 + (t >> 2);
            float w0 = W[(size_t)k0 * FOURU + n];
            float w1 = W[(size_t)(k0 + 1) * FOURU + n];
            hi[nblk * 2 + reg] = pack_split_hi(w0, w1);
            lo[nblk * 2 + reg] = pack_split_lo(w0, w1);
        }
    size_t wb = (((size_t)ks * 2 + 0) * 64 + ngrp) * 32 + t;
    size_t wl = (((size_t)ks * 2 + 1) * 64 + ngrp) * 32 + t;
    g_Wfrag[wb * 2]     = make_uint4(hi[0], hi[1], hi[2], hi[3]);
    g_Wfrag[wb * 2 + 1] = make_uint4(hi[4], hi[5], hi[6], hi[7]);
    g_Wfrag[wl * 2]     = make_uint4(lo[0], lo[1], lo[2], lo[3]);
    g_Wfrag[wl * 2 + 1] = make_uint4(lo[4], lo[5], lo[6], lo[7]);
}

#define MMA16816(c, a, b0v, b1v)                                              \
    asm volatile(                                                             \
        "mma.sync.aligned.m16n8k16.row.col.f32.bf16.bf16.f32 "                \
        "{%0,%1,%2,%3}, {%4,%5,%6,%7}, {%8,%9}, {%0,%1,%2,%3};"               \
        : "+f"((c)[0]), "+f"((c)[1]), "+f"((c)[2]), "+f"((c)[3])              \
        : "r"((a).x), "r"((a).y), "r"((a).z), "r"((a).w),                     \
          "r"(b0v), "r"(b1v))

// ---- GEMM (unchanged) ------------------------------------------------------
__global__ __launch_bounds__(256) void gemm_mma(const float* __restrict__ bias) {
    const int tid = threadIdx.x;
    const int t = tid & 31, wid = tid >> 5;
    const int wm = wid & 1, wn = wid >> 1;
    const int mtb = blockIdx.y * 8 + wm * 4;
    const int ngrp = blockIdx.x * 4 + wn;

    float acc[4][4][4];
#pragma unroll
    for (int mi = 0; mi < 4; mi++)
#pragma unroll
        for (int ni = 0; ni < 4; ni++)
#pragma unroll
            for (int c = 0; c < 4; c++) acc[mi][ni][c] = 0.f;

#pragma unroll 2
    for (int ks = 0; ks < NKSTEP; ks++) {
        uint4 ah[4], al[4];
#pragma unroll
        for (int mi = 0; mi < 4; mi++) {
            size_t ib = ((size_t)(mtb + mi) * 32 + ks) * 2;
            ah[mi] = g_Afrag[ib * 32 + t];
            al[mi] = g_Afrag[(ib + 1) * 32 + t];
        }
        size_t wb = (((size_t)ks * 2 + 0) * 64 + ngrp) * 32 + t;
        size_t wl = (((size_t)ks * 2 + 1) * 64 + ngrp) * 32 + t;
        uint4 bh0 = g_Wfrag[wb * 2], bh1 = g_Wfrag[wb * 2 + 1];
        uint4 bl0 = g_Wfrag[wl * 2], bl1 = g_Wfrag[wl * 2 + 1];
        uint32_t bh[8] = {bh0.x, bh0.y, bh0.z, bh0.w, bh1.x, bh1.y, bh1.z, bh1.w};
        uint32_t bl[8] = {bl0.x, bl0.y, bl0.z, bl0.w, bl1.x, bl1.y, bl1.z, bl1.w};

#pragma unroll
        for (int mi = 0; mi < 4; mi++)
#pragma unroll
            for (int ni = 0; ni < 4; ni++) {
                MMA16816(acc[mi][ni], ah[mi], bh[ni * 2], bh[ni * 2 + 1]);
                MMA16816(acc[mi][ni], ah[mi], bl[ni * 2], bl[ni * 2 + 1]);
                MMA16816(acc[mi][ni], al[mi], bh[ni * 2], bh[ni * 2 + 1]);
            }
    }

    const int colbase = blockIdx.x * 128 + wn * 32 + (t & 3) * 2;
    const int rowbase = blockIdx.y * 128 + wm * 64 + (t >> 2);
    float2 bv[4];
#pragma unroll
    for (int ni = 0; ni < 4; ni++)
        bv[ni] = *(const float2*)(bias + colbase + ni * 8);
#pragma unroll
    for (int mi = 0; mi < 4; mi++) {
        int r0 = rowbase + mi * 16;
#pragma unroll
        for (int ni = 0; ni < 4; ni++) {
            int col = colbase + ni * 8;
            float2 o0 = make_float2(acc[mi][ni][0] + bv[ni].x,
                                    acc[mi][ni][1] + bv[ni].y);
            float2 o1 = make_float2(acc[mi][ni][2] + bv[ni].x,
                                    acc[mi][ni][3] + bv[ni].y);
            __stcs((float2*)(g_xz + (size_t)r0 * FOURU + col), o0);
            __stcs((float2*)(g_xz + (size_t)(r0 + 8) * FOURU + col), o1);
        }
    }
}

// ---- persistent LSTM recurrence: 128 CTAs x 512 thr, k-split halves --------
// CTA (ug,bg): units [16ug,+16), batches [16bg,+16). half = tid>>8.
// Compute thread (half, u_l, b_l) covers kq in [half*64, half*64+64).
__global__ __launch_bounds__(TPB, 1) void lstm_recur(const float* __restrict__ R)
{
    extern __shared__ float sm[];
    float* R4  = sm + SM_R4;
    float* h4  = sm + SM_H4;
    float* xzs = sm + SM_XZ;
    float* red = sm + SM_RED;

    const int tid = threadIdx.x;
    const int ug = blockIdx.x >> 2, bg = blockIdx.x & 3;
    const int u0 = ug * 16, b0 = bg * 16;
    const int half = tid >> 8, rest = tid & 255;
    const int b_l = rest & 15, u_l = rest >> 4;

    for (int i = tid; i < 32768; i += TPB) {
        int kq = i >> 8, u = (i >> 4) & 15, e = i & 15, g = e >> 2, kl = e & 3;
        R4[i] = R[(size_t)(kq * 4 + kl) * FOURU + g * UNITS + u0 + u];
    }

    // xz staging (tid<256): thread -> (pb, pg, pq)
    const int pb = rest >> 4, pg = (rest >> 2) & 3, pq = rest & 3;
    const float* xz_thread = g_xz + (size_t)(b0 + pb) * TSTEPS * FOURU
                             + pg * UNITS + u0 + pq * 4;
    if (half == 0) {
        float4 v = __ldcs((const float4*)xz_thread);
        float vv[4] = {v.x, v.y, v.z, v.w};
#pragma unroll
        for (int j = 0; j < 4; j++)
            xzs[pg * 272 + (pq * 4 + j) * 17 + pb] = vv[j];
    }
    __syncthreads();

    unsigned* arrive = &g_arrive[bg * 32];
    unsigned* gen    = &g_gen[bg * 32];

    float c_state = 0.f;

    for (int t = 0; t < TSTEPS; t++) {
        float4 xnext = make_float4(0.f, 0.f, 0.f, 0.f);
        if (half == 0 && t + 1 < TSTEPS)
            xnext = __ldcs((const float4*)(xz_thread + (size_t)(t + 1) * FOURU));

        // ---- stage h(t): 512 thr x 4 float4, coalesced (consecutive kq per b)
        float4 hv[4];
#pragma unroll
        for (int r = 0; r < 4; r++) {
            int i = r * 512 + tid;
            hv[r] = __ldcg((const float4*)(&g_h[t & 1][b0 + (i >> 7)][(i & 127) * 4]));
        }
#pragma unroll
        for (int r = 0; r < 4; r++) {
            int i = r * 512 + tid;
            *(float4*)&h4[(i & 127) * 68 + (i >> 7) * 4] = hv[r];
        }
        __syncthreads();

        // ---- this half's 64 kq
        u64t a0 = 0ull, a1 = 0ull, a2 = 0ull, a3 = 0ull;
        const float* hrow = h4 + b_l * 4;
        const float* rrow = R4 + u_l * 16;
        const int kq0 = half * 64;
#pragma unroll 8
        for (int kq = kq0; kq < kq0 + 64; kq++) {
            ulonglong2 hh = *(const ulonglong2*)(hrow + kq * 68);
            ulonglong2 r0 = *(const ulonglong2*)(rrow + kq * 256);
            ulonglong2 r1 = *(const ulonglong2*)(rrow + kq * 256 + 4);
            ulonglong2 r2 = *(const ulonglong2*)(rrow + kq * 256 + 8);
            ulonglong2 r3 = *(const ulonglong2*)(rrow + kq * 256 + 12);
            ffma2(a0, r0.x, hh.x); ffma2(a1, r1.x, hh.x);
            ffma2(a2, r2.x, hh.x); ffma2(a3, r3.x, hh.x);
            ffma2(a0, r0.y, hh.y); ffma2(a1, r1.y, hh.y);
            ffma2(a2, r2.y, hh.y); ffma2(a3, r3.y, hh.y);
        }

        // ---- half1 publishes partials
        if (half == 1) {
            float* rb = red + rest * 12;
            *(ulonglong2*)rb       = make_ulonglong2(a0, a1);
            *(ulonglong2*)(rb + 4) = make_ulonglong2(a2, a3);
        }
        __syncthreads();

        if (half == 0) {
            const float* rb = red + rest * 12;
            ulonglong2 p01 = *(const ulonglong2*)rb;
            ulonglong2 p23 = *(const ulonglong2*)(rb + 4);
            float2 q, w;
            const float* xb = xzs + (t & 1) * 1088 + u_l * 17 + b_l;
            q = unpack2(a0); w = unpack2(p01.x);
            float z1 = q.x + q.y + w.x + w.y + xb[0];
            q = unpack2(a1); w = unpack2(p01.y);
            float z2 = q.x + q.y + w.x + w.y + xb[272];
            q = unpack2(a2); w = unpack2(p23.x);
            float z3 = q.x + q.y + w.x + w.y + xb[544];
            q = unpack2(a3); w = unpack2(p23.y);
            float z4 = q.x + q.y + w.x + w.y + xb[816];

            float v1 = ftanh(z1);
            float v2 = fsig(z2);
            float v3 = fsig(z3);
            float v4 = fsig(z4);
            c_state = v1 * v2 + v3 * c_state;
            float hnew = v4 * ftanh(c_state);
            __stcg(&g_h[(t + 1) & 1][b0 + b_l][u0 + u_l], hnew);
        }

        // ---- arrive early (publishes h via acq_rel), stage xz, then poll
        __syncthreads();
        if (tid == 0) {
            unsigned prev = atom_add_acqrel(arrive, 1u);
            if ((prev & 31u) == 31u)
                st_release(gen, (unsigned)(t + 1));
        }
        if (half == 0 && t + 1 < TSTEPS) {
            float vv[4] = {xnext.x, xnext.y, xnext.z, xnext.w};
            float* dst = xzs + ((t + 1) & 1) * 1088;
#pragma unroll
            for (int j = 0; j < 4; j++)
                dst[pg * 272 + (pq * 4 + j) * 17 + pb] = vv[j];
        }
        if (tid == 0) {
            while (ld_acquire(gen) < (unsigned)(t + 1)) { }
        }
        __syncthreads();
    }
}

// ---- final dense + softmax --------------------------------------------------
__global__ void fc_softmax(const float* __restrict__ fc_w,
                           const float* __restrict__ fc_b,
                           float* __restrict__ out)
{
    const int b = blockIdx.x;
    const int l = threadIdx.x;
    float a0 = 0.f, a1 = 0.f, a2 = 0.f, a3 = 0.f;
    const float* hg = &g_h[0][b][0];
    for (int k = l * 16; k < l * 16 + 16; k += 4) {
        float4 hv = *(const float4*)(hg + k);
        float hx[4] = {hv.x, hv.y, hv.z, hv.w};
#pragma unroll
        for (int q = 0; q < 4; q++) {
            float4 wv = *(const float4*)&fc_w[(k + q) * 4];
            a0 += hx[q] * wv.x; a1 += hx[q] * wv.y;
            a2 += hx[q] * wv.z; a3 += hx[q] * wv.w;
        }
    }
#pragma unroll
    for (int o = 16; o > 0; o >>= 1) {
        a0 += __shfl_down_sync(0xffffffffu, a0, o);
        a1 += __shfl_down_sync(0xffffffffu, a1, o);
        a2 += __shfl_down_sync(0xffffffffu, a2, o);
        a3 += __shfl_down_sync(0xffffffffu, a3, o);
    }
    if (l == 0) {
        float z0 = a0 + fc_b[0], z1 = a1 + fc_b[1];
        float z2 = a2 + fc_b[2], z3 = a3 + fc_b[3];
        float m = fmaxf(fmaxf(z0, z1), fmaxf(z2, z3));
        float e0 = __expf(z0 - m), e1 = __expf(z1 - m);
        float e2 = __expf(z2 - m), e3 = __expf(z3 - m);
        float inv = __fdividef(1.f, e0 + e1 + e2 + e3);
        out[b * 4 + 0] = e0 * inv;
        out[b * 4 + 1] = e1 * inv;
        out[b * 4 + 2] = e2 * inv;
        out[b * 4 + 3] = e3 * inv;
    }
}

// ---------------------------------------------------------------------------
extern "C" void kernel_launch(void* const* d_in, const int* in_sizes, int n_in,
                              void* d_out, int out_size)
{
    const float* tx      = (const float*)d_in[0];
    const float* kernelW = (const float*)d_in[1];
    const float* R       = (const float*)d_in[2];
    const float* bias    = (const float*)d_in[3];
    const float* fc_w    = (const float*)d_in[4];
    const float* fc_b    = (const float*)d_in[5];
    float* out           = (float*)d_out;

    cudaFuncSetAttribute(lstm_recur,
                         cudaFuncAttributeMaxDynamicSharedMemorySize, SM_BYTES);

    init_kernel<<<(2 * BATCH * UNITS + 255) / 256, 256>>>();
    prep_A<<<16384, 256>>>(tx);
    prep_W<<<256, 256>>>(kernelW);
    gemm_mma<<<dim3(16, 512), 256>>>(bias);
    lstm_recur<<<NCTA, TPB, SM_BYTES>>>(R);
    fc_softmax<<<BATCH, 32>>>(fc_w, fc_b, out);
    (void)in_sizes; (void)n_in; (void)out_size;
}